// round 6
// baseline (speedup 1.0000x reference)
#include <cuda_runtime.h>
#include <cstdint>

#define NQ 2048
#define NT 5
#define NB 32
#define TPB 128          // 4 warps per CTA
#define NCAND 3125       // 5^5

// Cross-CTA scratch (device globals: allocation-free, zero-initialized once).
__device__ unsigned long long g_sel[NB][NT][NT];  // packed (cost_bits<<32 | q)
__device__ int g_cnt[NB];                          // arrival counters (self-reset)

static __device__ __forceinline__ unsigned long long umin64(unsigned long long a,
                                                            unsigned long long b) {
    return a < b ? a : b;
}
static __device__ __forceinline__ unsigned long long umax64(unsigned long long a,
                                                            unsigned long long b) {
    return a > b ? a : b;
}
#define CE(a, b) { unsigned long long _lo = umin64(a, b); b = umax64(a, b); a = _lo; }

__global__ __launch_bounds__(TPB, 1)
void hungarian_match_kernel(const float* __restrict__ pred_regs,   // [32,2048,3]
                            const float* __restrict__ tgt,         // [160,3]
                            float* __restrict__ out)               // [2,32,5] f32
{
    __shared__ unsigned long long sm_lists[TPB / 32][NT];
    __shared__ int   sm_doit;
    __shared__ int   sel_idx[NT][NT];
    __shared__ float sel_val[NT][NT];
    __shared__ unsigned long long red[TPB / 32];

    const int cta  = blockIdx.x;
    const int b    = cta / NT;
    const int t    = cta - b * NT;
    const int tid  = threadIdx.x;
    const int w    = tid >> 5;
    const int lane = tid & 31;

    // ---- target coords (broadcast load) ----
    const float t0f = __ldg(&tgt[b * NT * 3 + t * 3 + 0]);
    const float t1f = __ldg(&tgt[b * NT * 3 + t * 3 + 1]);
    const float t2f = __ldg(&tgt[b * NT * 3 + t * 3 + 2]);

    // ---- per-lane single-pass top-5 over 16 queries (bit-exact XLA cost) ----
    // key = float_bits(cost)<<32 | q ; costs >= 1 > 0 so uint order == float
    // order and the embedded q reproduces jax.lax.top_k's stable tie-break.
    const float* pr = pred_regs + (size_t)b * NQ * 3;
    unsigned long long m0 = ~0ULL, m1 = ~0ULL, m2 = ~0ULL, m3 = ~0ULL, m4 = ~0ULL;
    #pragma unroll
    for (int i = 0; i < NQ / TPB; i++) {
        int q = tid + i * TPB;
        float p0 = __ldg(&pr[q * 3 + 0]);
        float p1 = __ldg(&pr[q * 3 + 1]);
        float p2 = __ldg(&pr[q * 3 + 2]);
        float a0 = fabsf(__fsub_rn(p0, t0f));
        float a1 = fabsf(__fsub_rn(p1, t1f));
        float a2 = fabsf(__fsub_rn(p2, t2f));
        float c  = __fadd_rn(__fadd_rn(__fadd_rn(a0, a1), a2), 1.0f);
        unsigned long long key =
            ((unsigned long long)__float_as_uint(c) << 32) | (unsigned int)q;
        if (key < m4) {
            m4 = key;
            unsigned long long tmp;
            if (m4 < m3) { tmp = m3; m3 = m4; m4 = tmp; }
            if (m3 < m2) { tmp = m2; m2 = m3; m3 = tmp; }
            if (m2 < m1) { tmp = m1; m1 = m2; m2 = tmp; }
            if (m1 < m0) { tmp = m0; m0 = m1; m1 = tmp; }
        }
    }

    // ---- warp bitonic merge: 5 levels, keep 5 smallest, re-sort (9-CE) ----
    #pragma unroll
    for (int off = 16; off > 0; off >>= 1) {
        unsigned long long o0 = __shfl_xor_sync(0xffffffffu, m0, off);
        unsigned long long o1 = __shfl_xor_sync(0xffffffffu, m1, off);
        unsigned long long o2 = __shfl_xor_sync(0xffffffffu, m2, off);
        unsigned long long o3 = __shfl_xor_sync(0xffffffffu, m3, off);
        unsigned long long o4 = __shfl_xor_sync(0xffffffffu, m4, off);
        unsigned long long s0 = umin64(m0, o4);
        unsigned long long s1 = umin64(m1, o3);
        unsigned long long s2 = umin64(m2, o2);
        unsigned long long s3 = umin64(m3, o1);
        unsigned long long s4 = umin64(m4, o0);
        CE(s0, s1); CE(s3, s4); CE(s2, s4); CE(s2, s3); CE(s0, s3);
        CE(s0, s2); CE(s1, s4); CE(s1, s3); CE(s1, s2);
        m0 = s0; m1 = s1; m2 = s2; m3 = s3; m4 = s4;
    }
    if (lane == 0) {
        sm_lists[w][0] = m0; sm_lists[w][1] = m1; sm_lists[w][2] = m2;
        sm_lists[w][3] = m3; sm_lists[w][4] = m4;
    }
    __syncthreads();

    // ---- thread 0: 4-way merge of sorted 5-lists -> top-5; publish; count ----
    if (tid == 0) {
        int pos[4] = {0, 0, 0, 0};
        #pragma unroll
        for (int k = 0; k < NT; k++) {
            unsigned long long best = ~0ULL;
            int bi = 0;
            #pragma unroll
            for (int ww = 0; ww < TPB / 32; ww++) {
                unsigned long long v = sm_lists[ww][pos[ww]];
                if (v < best) { best = v; bi = ww; }
            }
            pos[bi]++;
            g_sel[b][t][k] = best;
        }
        __threadfence();
        int old = atomicAdd(&g_cnt[b], 1);
        sm_doit = (old == NT - 1) ? 1 : 0;
    }
    __syncthreads();
    if (!sm_doit) return;

    // ======== last CTA for batch b: enumeration + output ========
    __threadfence();   // order the g_sel loads below after the counter observe
    if (tid < NT * NT) {
        unsigned long long v = g_sel[b][tid / NT][tid % NT];
        sel_idx[tid / NT][tid % NT] = (int)(unsigned int)v;
        sel_val[tid / NT][tid % NT] = __uint_as_float((unsigned int)(v >> 32));
    }
    if (tid == 0) g_cnt[b] = 0;   // self-reset for next graph replay
    __syncthreads();

    // ---- 3125 tuples; argmin of f32 sum, first-occurrence tie-break ----
    unsigned long long best = ~0ULL;
    for (int n = tid; n < NCAND; n += TPB) {
        int r  = n;
        int d0 = r / 625;  r -= d0 * 625;
        int d1 = r / 125;  r -= d1 * 125;
        int d2 = r / 25;   r -= d2 * 25;
        int d3 = r / 5;
        int d4 = r - d3 * 5;
        int q0 = sel_idx[0][d0], q1 = sel_idx[1][d1], q2 = sel_idx[2][d2],
            q3 = sel_idx[3][d3], q4 = sel_idx[4][d4];
        bool valid = (q0 != q1) && (q0 != q2) && (q0 != q3) && (q0 != q4) &&
                     (q1 != q2) && (q1 != q3) && (q1 != q4) &&
                     (q2 != q3) && (q2 != q4) && (q3 != q4);
        if (valid) {
            float tot = __fadd_rn(
                            __fadd_rn(
                                __fadd_rn(
                                    __fadd_rn(sel_val[0][d0], sel_val[1][d1]),
                                    sel_val[2][d2]),
                                sel_val[3][d3]),
                            sel_val[4][d4]);
            unsigned long long key =
                ((unsigned long long)__float_as_uint(tot) << 32) | (unsigned int)n;
            best = umin64(best, key);
        }
    }
    #pragma unroll
    for (int s = 16; s > 0; s >>= 1)
        best = umin64(best, __shfl_xor_sync(0xffffffffu, best, s));
    if (lane == 0) red[w] = best;
    __syncthreads();

    if (tid == 0) {
        unsigned long long bb = red[0];
        #pragma unroll
        for (int i = 1; i < TPB / 32; i++) bb = umin64(bb, red[i]);
        int n = (int)(unsigned int)bb;
        int d[NT];
        d[0] = n / 625; n %= 625;
        d[1] = n / 125; n %= 125;
        d[2] = n / 25;  n %= 25;
        d[3] = n / 5;
        d[4] = n % 5;
        int rows[NT], cols[NT];
        #pragma unroll
        for (int j = 0; j < NT; j++) { rows[j] = sel_idx[j][d[j]]; cols[j] = j; }
        #pragma unroll
        for (int i = 1; i < NT; i++) {     // stable insertion sort by rows
            int rv = rows[i], cv = cols[i], j = i - 1;
            while (j >= 0 && rows[j] > rv) {
                rows[j + 1] = rows[j]; cols[j + 1] = cols[j]; j--;
            }
            rows[j + 1] = rv; cols[j + 1] = cv;
        }
        #pragma unroll
        for (int j = 0; j < NT; j++) {
            out[b * NT + j]           = (float)rows[j];   // output 0: rows [32,5]
            out[NB * NT + b * NT + j] = (float)cols[j];   // output 1: cols [32,5]
        }
    }
}

extern "C" void kernel_launch(void* const* d_in, const int* in_sizes, int n_in,
                              void* d_out, int out_size) {
    // Bind by size (confirmed working): pred_regs = 196608 f32, tgt = 480 f32.
    int pr_i = -1, tg_i = -1, max_i = 0;
    for (int i = 0; i < n_in; i++) {
        if (in_sizes[i] == 196608 || in_sizes[i] == 786432) pr_i = i;
        if (in_sizes[i] == 480    || in_sizes[i] == 1920)   tg_i = i;
        if (in_sizes[i] > in_sizes[max_i]) max_i = i;
    }
    if (pr_i < 0) pr_i = max_i;
    if (tg_i < 0) tg_i = (n_in > 3) ? 3 : n_in - 1;

    const float* pred_regs = (const float*)d_in[pr_i];
    const float* tgt       = (const float*)d_in[tg_i];
    float* out = (float*)d_out;
    hungarian_match_kernel<<<NB * NT, TPB>>>(pred_regs, tgt, out);
}

// round 7
// speedup vs baseline: 1.1805x; 1.1805x over previous
#include <cuda_runtime.h>
#include <cstdint>

#define NQ 2048
#define NT 5
#define NB 32
#define NCH 4                 // chunks per target
#define NW (NT * NCH)         // 20 warps
#define TPB (NW * 32)         // 640 threads
#define QCHUNK (NQ / NCH)     // 512 queries per warp
#define NCAND 3125            // 5^5

static __device__ __forceinline__ unsigned long long umin64(unsigned long long a,
                                                            unsigned long long b) {
    return a < b ? a : b;
}
static __device__ __forceinline__ unsigned long long umax64(unsigned long long a,
                                                            unsigned long long b) {
    return a > b ? a : b;
}
#define CE(a, b) { unsigned long long _lo = umin64(a, b); b = umax64(a, b); a = _lo; }

// Merge two sorted-ascending 5-lists, keep the 5 smallest (sorted) in a[].
// Keys are unique (query index embedded) so multiset semantics are exact.
static __device__ __forceinline__ void merge_top5(unsigned long long* a,
                                                  const unsigned long long* b) {
    unsigned long long s0 = umin64(a[0], b[4]);
    unsigned long long s1 = umin64(a[1], b[3]);
    unsigned long long s2 = umin64(a[2], b[2]);
    unsigned long long s3 = umin64(a[3], b[1]);
    unsigned long long s4 = umin64(a[4], b[0]);
    CE(s0, s1); CE(s3, s4); CE(s2, s4); CE(s2, s3); CE(s0, s3);
    CE(s0, s2); CE(s1, s4); CE(s1, s3); CE(s1, s2);
    a[0] = s0; a[1] = s1; a[2] = s2; a[3] = s3; a[4] = s4;
}

__global__ __launch_bounds__(TPB, 1)
void hungarian_match_kernel(const float* __restrict__ pred_regs,   // [32,2048,3]
                            const float* __restrict__ tgt,         // [160,3]
                            float* __restrict__ out)               // [2,32,5] f32
{
    __shared__ unsigned long long sm_lists[NW][NT];
    __shared__ int   sel_idx[NT][NT];
    __shared__ float sel_val[NT][NT];
    __shared__ unsigned long long red[NW];

    const int b    = blockIdx.x;
    const int tid  = threadIdx.x;
    const int w    = tid >> 5;
    const int lane = tid & 31;
    const int t    = w >> 2;      // target 0..4
    const int ch   = w & 3;       // chunk 0..3

    // ---- target coords for this warp (broadcast) ----
    const float t0f = __ldg(&tgt[b * NT * 3 + t * 3 + 0]);
    const float t1f = __ldg(&tgt[b * NT * 3 + t * 3 + 1]);
    const float t2f = __ldg(&tgt[b * NT * 3 + t * 3 + 2]);

    // ---- per-lane single-pass top-5 over 16 queries (bit-exact XLA cost) ----
    // key = float_bits(cost)<<32 | q ; costs >= 1 > 0 so uint order == float
    // order; embedded q reproduces jax.lax.top_k's stable tie-break.
    const float* pr = pred_regs + (size_t)b * NQ * 3;
    unsigned long long m[NT] = {~0ULL, ~0ULL, ~0ULL, ~0ULL, ~0ULL};
    const int qbase = ch * QCHUNK + lane;
    #pragma unroll
    for (int i = 0; i < QCHUNK / 32; i++) {
        int q = qbase + i * 32;
        float p0 = __ldg(&pr[q * 3 + 0]);
        float p1 = __ldg(&pr[q * 3 + 1]);
        float p2 = __ldg(&pr[q * 3 + 2]);
        float a0 = fabsf(__fsub_rn(p0, t0f));
        float a1 = fabsf(__fsub_rn(p1, t1f));
        float a2 = fabsf(__fsub_rn(p2, t2f));
        float c  = __fadd_rn(__fadd_rn(__fadd_rn(a0, a1), a2), 1.0f);
        unsigned long long key =
            ((unsigned long long)__float_as_uint(c) << 32) | (unsigned int)q;
        if (key < m[4]) {
            m[4] = key;
            unsigned long long tmp;
            if (m[4] < m[3]) { tmp = m[3]; m[3] = m[4]; m[4] = tmp; }
            if (m[3] < m[2]) { tmp = m[2]; m[2] = m[3]; m[3] = tmp; }
            if (m[2] < m[1]) { tmp = m[1]; m[1] = m[2]; m[2] = tmp; }
            if (m[1] < m[0]) { tmp = m[0]; m[0] = m[1]; m[1] = tmp; }
        }
    }

    // ---- warp bitonic merge: 5 levels; every lane ends with warp top-5 ----
    #pragma unroll
    for (int off = 16; off > 0; off >>= 1) {
        unsigned long long o[NT];
        #pragma unroll
        for (int k = 0; k < NT; k++)
            o[NT - 1 - k] = __shfl_xor_sync(0xffffffffu, m[k], off);
        // o[] is now the partner's list reversed (descending): merge_top5 form
        merge_top5(m, o);
    }
    if (lane == 0) {
        #pragma unroll
        for (int k = 0; k < NT; k++) sm_lists[w][k] = m[k];
    }
    __syncthreads();

    // ---- threads 0..4: register-resident 4-way merge for target tid ----
    if (tid < NT) {
        unsigned long long A[NT], B[NT];
        #pragma unroll
        for (int k = 0; k < NT; k++) A[k] = sm_lists[tid * NCH + 0][k];
        #pragma unroll
        for (int j = 1; j < NCH; j++) {
            #pragma unroll
            for (int k = 0; k < NT; k++) B[NT - 1 - k] = sm_lists[tid * NCH + j][k];
            merge_top5(A, B);   // B passed reversed (descending)
        }
        #pragma unroll
        for (int k = 0; k < NT; k++) {
            sel_idx[tid][k] = (int)(unsigned int)A[k];
            sel_val[tid][k] = __uint_as_float((unsigned int)(A[k] >> 32));
        }
    }
    __syncthreads();

    // ---- 3125 tuples over 640 threads; argmin of f32 sum, first-occurrence ----
    unsigned long long best = ~0ULL;
    for (int n = tid; n < NCAND; n += TPB) {
        int r  = n;
        int d0 = r / 625;  r -= d0 * 625;
        int d1 = r / 125;  r -= d1 * 125;
        int d2 = r / 25;   r -= d2 * 25;
        int d3 = r / 5;
        int d4 = r - d3 * 5;
        int q0 = sel_idx[0][d0], q1 = sel_idx[1][d1], q2 = sel_idx[2][d2],
            q3 = sel_idx[3][d3], q4 = sel_idx[4][d4];
        bool valid = (q0 != q1) && (q0 != q2) && (q0 != q3) && (q0 != q4) &&
                     (q1 != q2) && (q1 != q3) && (q1 != q4) &&
                     (q2 != q3) && (q2 != q4) && (q3 != q4);
        if (valid) {
            float tot = __fadd_rn(
                            __fadd_rn(
                                __fadd_rn(
                                    __fadd_rn(sel_val[0][d0], sel_val[1][d1]),
                                    sel_val[2][d2]),
                                sel_val[3][d3]),
                            sel_val[4][d4]);
            unsigned long long key =
                ((unsigned long long)__float_as_uint(tot) << 32) | (unsigned int)n;
            best = umin64(best, key);
        }
    }
    #pragma unroll
    for (int s = 16; s > 0; s >>= 1)
        best = umin64(best, __shfl_xor_sync(0xffffffffu, best, s));
    if (lane == 0) red[w] = best;
    __syncthreads();

    // ---- thread 0: decode winner, stable sort, write float output ----
    if (tid == 0) {
        unsigned long long bb = red[0];
        #pragma unroll
        for (int i = 1; i < NW; i++) bb = umin64(bb, red[i]);
        int n = (int)(unsigned int)bb;
        int d[NT];
        d[0] = n / 625; n %= 625;
        d[1] = n / 125; n %= 125;
        d[2] = n / 25;  n %= 25;
        d[3] = n / 5;
        d[4] = n % 5;
        int rows[NT], cols[NT];
        #pragma unroll
        for (int j = 0; j < NT; j++) { rows[j] = sel_idx[j][d[j]]; cols[j] = j; }
        #pragma unroll
        for (int i = 1; i < NT; i++) {     // stable insertion sort by rows
            int rv = rows[i], cv = cols[i], j = i - 1;
            while (j >= 0 && rows[j] > rv) {
                rows[j + 1] = rows[j]; cols[j + 1] = cols[j]; j--;
            }
            rows[j + 1] = rv; cols[j + 1] = cv;
        }
        #pragma unroll
        for (int j = 0; j < NT; j++) {
            out[b * NT + j]           = (float)rows[j];   // output 0: rows [32,5]
            out[NB * NT + b * NT + j] = (float)cols[j];   // output 1: cols [32,5]
        }
    }
}

extern "C" void kernel_launch(void* const* d_in, const int* in_sizes, int n_in,
                              void* d_out, int out_size) {
    // Bind by size (confirmed working): pred_regs = 196608 f32, tgt = 480 f32.
    int pr_i = -1, tg_i = -1, max_i = 0;
    for (int i = 0; i < n_in; i++) {
        if (in_sizes[i] == 196608 || in_sizes[i] == 786432) pr_i = i;
        if (in_sizes[i] == 480    || in_sizes[i] == 1920)   tg_i = i;
        if (in_sizes[i] > in_sizes[max_i]) max_i = i;
    }
    if (pr_i < 0) pr_i = max_i;
    if (tg_i < 0) tg_i = (n_in > 3) ? 3 : n_in - 1;

    const float* pred_regs = (const float*)d_in[pr_i];
    const float* tgt       = (const float*)d_in[tg_i];
    float* out = (float*)d_out;
    hungarian_match_kernel<<<NB, TPB>>>(pred_regs, tgt, out);
}